// round 4
// baseline (speedup 1.0000x reference)
#include <cuda_runtime.h>
#include <math.h>
#include <stdint.h>

// SAGAN SelfAttention: B=16, C=512, H=W=64, HW=4096, HW4=1024, C8=64, C2=256
#define NB 16

// Fragment-permuted tf32 scratch (unsigned = tf32 bit patterns)
// S8 split layout (per k8 group, 16 slots): pos = (k&3)*4 + ((k>>2)&1)*2 + s   (s=0 hi, 1 lo)
// P16 plain layout (per k16 group, 16 slots): pos = (k&3)*4 + ((k>>3)&1)*2 + ((k>>2)&1)
__device__ __align__(128) unsigned g_theta_u[(size_t)NB * 64 * 8 * 64 * 16];   // [b][pt][k8][r64][16]  split
__device__ __align__(128) unsigned g_phi_u  [(size_t)NB * 8 * 8 * 128 * 16];   // [b][mc][k8][c128][16] split
__device__ __align__(128) unsigned g_gv_u   [(size_t)NB * 64 * 256 * 16];      // [b][g16][co256][16]   plain
__device__ __align__(128) unsigned g_ag_u   [(size_t)NB * 32 * 16 * 128 * 16]; // [b][pt2][g16][r128][16] plain

__device__ __forceinline__ unsigned f2tf(float f) {
    unsigned r; asm("cvt.rna.tf32.f32 %0,%1;" : "=r"(r) : "f"(f)); return r;
}
__device__ __forceinline__ void st_split(unsigned* d, float v) {
    unsigned hi; asm("cvt.rna.tf32.f32 %0,%1;" : "=r"(hi) : "f"(v));
    float rem = v - __uint_as_float(hi);
    unsigned lo; asm("cvt.rna.tf32.f32 %0,%1;" : "=r"(lo) : "f"(rem));
    d[0] = hi; d[1] = lo;
}
__device__ __forceinline__ void mma4(float d[4],
                                     unsigned a0, unsigned a1, unsigned a2, unsigned a3,
                                     unsigned b0, unsigned b1) {
    asm("mma.sync.aligned.m16n8k8.row.col.f32.tf32.tf32.f32 "
        "{%0,%1,%2,%3},{%4,%5,%6,%7},{%8,%9},{%0,%1,%2,%3};"
        : "+f"(d[0]), "+f"(d[1]), "+f"(d[2]), "+f"(d[3])
        : "r"(a0), "r"(a1), "r"(a2), "r"(a3), "r"(b0), "r"(b1));
}

// ---------------------------------------------------------------------------
// conv0: theta (rows 0-63) + phi (rows 64-127), K=512, 3xTF32.
// Block 256 thr, tile 128x128, k-step 32. Warps 2(m)x4(n), warp 64x32.
// dyn smem 64KB: As[4][128][16] | Bs[4][128][16], union stage[128][66]
// ---------------------------------------------------------------------------
__global__ void __launch_bounds__(256, 2)
conv0_kernel(const float* __restrict__ x,
             const float* __restrict__ wT, const float* __restrict__ wP,
             const float* __restrict__ bT, const float* __restrict__ bP)
{
    extern __shared__ unsigned smc[];
    unsigned* As = smc;
    unsigned* Bs = smc + 8192;
    float (*stage)[66] = (float(*)[66])smc;

    const int tid = threadIdx.x, lane = tid & 31, wid = tid >> 5;
    const int gq = lane >> 2, tq = lane & 3;
    const int wm = wid & 1, wn = wid >> 1;
    const int b = blockIdx.z, tb = blockIdx.x;
    const int n0 = tb * 128;
    const float* xb = x + ((size_t)b << 21);

    float acc[4][4][4] = {};

    for (int k0 = 0; k0 < 512; k0 += 32) {
        __syncthreads();
#pragma unroll
        for (int p = 0; p < 4; p++) {   // weights -> split
            int idx = tid + p * 256, r = idx >> 3, c4 = (idx & 7) << 2;
            const float* wp = (r < 64) ? wT + (size_t)r * 512 : wP + (size_t)(r - 64) * 512;
            float4 v = *(const float4*)(wp + k0 + c4);
            unsigned* d = As + (((c4 >> 3) * 128 + r) << 4) + (((c4 >> 2) & 1) << 1);
            st_split(d, v.x); st_split(d + 4, v.y); st_split(d + 8, v.z); st_split(d + 12, v.w);
        }
#pragma unroll
        for (int p = 0; p < 4; p++) {   // x -> split
            int idx = tid + p * 256, r = idx >> 5, c4 = (idx & 31) << 2;
            float4 v = *(const float4*)(xb + (size_t)(k0 + r) * 4096 + n0 + c4);
            unsigned* d = Bs + (((r >> 3) * 128 + c4) << 4) + ((r & 3) << 2) + (((r >> 2) & 1) << 1);
            st_split(d, v.x); st_split(d + 16, v.y); st_split(d + 32, v.z); st_split(d + 48, v.w);
        }
        __syncthreads();
#pragma unroll
        for (int k8 = 0; k8 < 4; k8++) {
            uint4 fa[4], fb[4], gg[4];
#pragma unroll
            for (int mt = 0; mt < 4; mt++) {
                int r0 = wm * 64 + mt * 16 + gq;
                fa[mt] = *(const uint4*)(As + ((k8 * 128 + r0) << 4) + (tq << 2));
                fb[mt] = *(const uint4*)(As + ((k8 * 128 + r0 + 8) << 4) + (tq << 2));
            }
#pragma unroll
            for (int nt = 0; nt < 4; nt++) {
                int c0 = wn * 32 + nt * 8 + gq;
                gg[nt] = *(const uint4*)(Bs + ((k8 * 128 + c0) << 4) + (tq << 2));
            }
#pragma unroll
            for (int mt = 0; mt < 4; mt++)
#pragma unroll
                for (int nt = 0; nt < 4; nt++) {
                    mma4(acc[mt][nt], fa[mt].x, fb[mt].x, fa[mt].z, fb[mt].z, gg[nt].x, gg[nt].z);
                    mma4(acc[mt][nt], fa[mt].x, fb[mt].x, fa[mt].z, fb[mt].z, gg[nt].y, gg[nt].w);
                    mma4(acc[mt][nt], fa[mt].y, fb[mt].y, fa[mt].w, fb[mt].w, gg[nt].x, gg[nt].z);
                }
        }
    }
    __syncthreads();

    // bias
#pragma unroll
    for (int mt = 0; mt < 4; mt++) {
        int R0 = wm * 64 + mt * 16 + gq, R1 = R0 + 8;
        float bv0 = (R0 < 64) ? bT[R0] : bP[R0 - 64];
        float bv1 = (R1 < 64) ? bT[R1] : bP[R1 - 64];
#pragma unroll
        for (int nt = 0; nt < 4; nt++) {
            acc[mt][nt][0] += bv0; acc[mt][nt][1] += bv0;
            acc[mt][nt][2] += bv1; acc[mt][nt][3] += bv1;
        }
    }

    if (wm == 0) {  // theta -> split, fragment layout [b][pt][k8][r][16]
#pragma unroll
        for (int mt = 0; mt < 4; mt++) {
            int R0 = mt * 16 + gq, R1 = R0 + 8;
            int k8a = R0 >> 3, pa = ((R0 & 3) << 2) + (((R0 >> 2) & 1) << 1);
            int k8b = R1 >> 3, pb = ((R1 & 3) << 2) + (((R1 >> 2) & 1) << 1);
#pragma unroll
            for (int nt = 0; nt < 4; nt++) {
                int col = n0 + wn * 32 + nt * 8 + 2 * tq;
                int pt = col >> 6, rw = col & 63;
                size_t base = (((size_t)b * 64 + pt) * 8) * 1024;
                st_split(g_theta_u + base + ((k8a * 64 + rw) << 4) + pa,     acc[mt][nt][0]);
                st_split(g_theta_u + base + ((k8a * 64 + rw + 1) << 4) + pa, acc[mt][nt][1]);
                st_split(g_theta_u + base + ((k8b * 64 + rw) << 4) + pb,     acc[mt][nt][2]);
                st_split(g_theta_u + base + ((k8b * 64 + rw + 1) << 4) + pb, acc[mt][nt][3]);
            }
        }
    } else {        // phi: w-pool in-register, stage for h-pool
#pragma unroll
        for (int mt = 0; mt < 4; mt++) {
            int r0 = 64 + mt * 16 + gq;
#pragma unroll
            for (int nt = 0; nt < 4; nt++) {
                int j = wn * 16 + nt * 4 + tq;
                stage[r0][j]     = fmaxf(acc[mt][nt][0], acc[mt][nt][1]);
                stage[r0 + 8][j] = fmaxf(acc[mt][nt][2], acc[mt][nt][3]);
            }
        }
    }
    __syncthreads();
    for (int idx = tid; idx < 64 * 32; idx += 256) {
        int co = idx >> 5, wp = idx & 31;
        float v = fmaxf(stage[64 + co][wp], stage[64 + co][wp + 32]);
        int m = tb * 32 + wp, mc = m >> 7, cm = m & 127;
        int k8 = co >> 3, pos = ((co & 3) << 2) + (((co >> 2) & 1) << 1);
        st_split(g_phi_u + ((((size_t)b * 8 + mc) * 8 + k8) * 128 + cm) * 16 + pos, v);
    }
}

// ---------------------------------------------------------------------------
// conv1: g conv, M=256 (grid.y=2), plain tf32, pooled -> g_gv_u [b][g16][co][16]
// dyn smem: As[2][128][16] | Bs[2][128][16] (32KB), union stage[128][66]
// ---------------------------------------------------------------------------
__global__ void __launch_bounds__(256, 2)
conv1_kernel(const float* __restrict__ x, const float* __restrict__ wG,
             const float* __restrict__ bG)
{
    extern __shared__ unsigned smc[];
    unsigned* As = smc;
    unsigned* Bs = smc + 4096;
    float (*stage)[66] = (float(*)[66])smc;

    const int tid = threadIdx.x, lane = tid & 31, wid = tid >> 5;
    const int gq = lane >> 2, tq = lane & 3;
    const int wm = wid & 1, wn = wid >> 1;
    const int b = blockIdx.z, tb = blockIdx.x;
    const int n0 = tb * 128, m0 = blockIdx.y * 128;
    const float* xb = x + ((size_t)b << 21);

    float acc[4][4][4] = {};

    for (int k0 = 0; k0 < 512; k0 += 32) {
        __syncthreads();
#pragma unroll
        for (int p = 0; p < 4; p++) {
            int idx = tid + p * 256, r = idx >> 3, c4 = (idx & 7) << 2;
            float4 v = *(const float4*)(wG + (size_t)(m0 + r) * 512 + k0 + c4);
            unsigned* d = As + (((c4 >> 4) * 128 + r) << 4) + (((c4 >> 3) & 1) << 1) + ((c4 >> 2) & 1);
            d[0] = f2tf(v.x); d[4] = f2tf(v.y); d[8] = f2tf(v.z); d[12] = f2tf(v.w);
        }
#pragma unroll
        for (int p = 0; p < 4; p++) {
            int idx = tid + p * 256, r = idx >> 5, c4 = (idx & 31) << 2;
            float4 v = *(const float4*)(xb + (size_t)(k0 + r) * 4096 + n0 + c4);
            unsigned* d = Bs + (((r >> 4) * 128 + c4) << 4) + ((r & 3) << 2) + (((r >> 3) & 1) << 1) + ((r >> 2) & 1);
            d[0] = f2tf(v.x); d[16] = f2tf(v.y); d[32] = f2tf(v.z); d[48] = f2tf(v.w);
        }
        __syncthreads();
#pragma unroll
        for (int g16 = 0; g16 < 2; g16++) {
            uint4 fa[4], fb[4], gg[4];
#pragma unroll
            for (int mt = 0; mt < 4; mt++) {
                int r0 = wm * 64 + mt * 16 + gq;
                fa[mt] = *(const uint4*)(As + ((g16 * 128 + r0) << 4) + (tq << 2));
                fb[mt] = *(const uint4*)(As + ((g16 * 128 + r0 + 8) << 4) + (tq << 2));
            }
#pragma unroll
            for (int nt = 0; nt < 4; nt++) {
                int c0 = wn * 32 + nt * 8 + gq;
                gg[nt] = *(const uint4*)(Bs + ((g16 * 128 + c0) << 4) + (tq << 2));
            }
#pragma unroll
            for (int mt = 0; mt < 4; mt++)
#pragma unroll
                for (int nt = 0; nt < 4; nt++) {
                    mma4(acc[mt][nt], fa[mt].x, fb[mt].x, fa[mt].y, fb[mt].y, gg[nt].x, gg[nt].y);
                    mma4(acc[mt][nt], fa[mt].z, fb[mt].z, fa[mt].w, fb[mt].w, gg[nt].z, gg[nt].w);
                }
        }
    }
    __syncthreads();

#pragma unroll
    for (int mt = 0; mt < 4; mt++) {
        int R0 = m0 + wm * 64 + mt * 16 + gq;
        float bv0 = bG[R0], bv1 = bG[R0 + 8];
#pragma unroll
        for (int nt = 0; nt < 4; nt++) {
            acc[mt][nt][0] += bv0; acc[mt][nt][1] += bv0;
            acc[mt][nt][2] += bv1; acc[mt][nt][3] += bv1;
        }
    }
#pragma unroll
    for (int mt = 0; mt < 4; mt++) {
        int r0 = wm * 64 + mt * 16 + gq;
#pragma unroll
        for (int nt = 0; nt < 4; nt++) {
            int j = wn * 16 + nt * 4 + tq;
            stage[r0][j]     = fmaxf(acc[mt][nt][0], acc[mt][nt][1]);
            stage[r0 + 8][j] = fmaxf(acc[mt][nt][2], acc[mt][nt][3]);
        }
    }
    __syncthreads();
    for (int idx = tid; idx < 128 * 32; idx += 256) {
        int wp = idx >> 7, r = idx & 127;
        float v = fmaxf(stage[r][wp], stage[r][wp + 32]);
        int co = m0 + r, m = tb * 32 + wp;
        int g16 = m >> 4;
        int pos = ((m & 3) << 2) + (((m >> 3) & 1) << 1) + ((m >> 2) & 1);
        g_gv_u[(((size_t)b * 64 + g16) * 256 + co) * 16 + pos] = f2tf(v);
    }
}

// ---------------------------------------------------------------------------
// attn: block = (b, 64 query rows). 8 warps: wm 0-1 rows, wn 0-3.
// S 64x128 3xTF32 (phi streamed in 2 k-halves), online softmax,
// PV 64x256 plain tf32 (G streamed 32 rows). Pure LDS.128 + HMMA mainloops.
// smem u32: Th[8][64][16] | Ps[8][64][16] | U[ (Ph-half[4][128][16] | Gs[2][256][16]) ] | red[4][64]f
// ---------------------------------------------------------------------------
__global__ void __launch_bounds__(256, 2)
attn_kernel()
{
    extern __shared__ unsigned smu[];
    unsigned* Th = smu;                 // 8192
    unsigned* Ps = smu + 8192;          // 8192
    unsigned* U  = smu + 16384;         // 8192
    float (*red)[64] = (float(*)[64])(smu + 24576);

    const int tid = threadIdx.x, lane = tid & 31, wid = tid >> 5;
    const int gq = lane >> 2, tq = lane & 3;
    const int wm = wid >> 2, wn = wid & 3;
    const int b = blockIdx.y, p0 = blockIdx.x * 64;

    {
        const uint4* src = (const uint4*)(g_theta_u + ((size_t)b * 64 + (p0 >> 6)) * 8192);
        uint4* dst = (uint4*)Th;
#pragma unroll
        for (int p = 0; p < 8; p++) dst[tid + p * 256] = src[tid + p * 256];
    }

    float oacc[2][8][4] = {};
    float rmax[2][2] = {{-INFINITY, -INFINITY}, {-INFINITY, -INFINITY}};
    float rsum[2][2] = {{0.f, 0.f}, {0.f, 0.f}};

    for (int mc = 0; mc < 8; mc++) {
        float sacc[2][4][4] = {};
        // ---- S = Th @ Ph, phi streamed in two 32-channel halves ----
#pragma unroll
        for (int kh = 0; kh < 2; kh++) {
            __syncthreads();
            {
                const uint4* src = (const uint4*)(g_phi_u + (((size_t)b * 8 + mc) * 8 + kh * 4) * 2048);
                uint4* dst = (uint4*)U;
#pragma unroll
                for (int p = 0; p < 8; p++) dst[tid + p * 256] = src[tid + p * 256];
            }
            __syncthreads();
#pragma unroll
            for (int k8l = 0; k8l < 4; k8l++) {
                int k8 = kh * 4 + k8l;
                uint4 fa[2], fb[2], gg[4];
#pragma unroll
                for (int mt = 0; mt < 2; mt++) {
                    int r0 = wm * 32 + mt * 16 + gq;
                    fa[mt] = *(const uint4*)(Th + ((k8 * 64 + r0) << 4) + (tq << 2));
                    fb[mt] = *(const uint4*)(Th + ((k8 * 64 + r0 + 8) << 4) + (tq << 2));
                }
#pragma unroll
                for (int nt = 0; nt < 4; nt++) {
                    int c0 = wn * 32 + nt * 8 + gq;
                    gg[nt] = *(const uint4*)(U + ((k8l * 128 + c0) << 4) + (tq << 2));
                }
#pragma unroll
                for (int mt = 0; mt < 2; mt++)
#pragma unroll
                    for (int nt = 0; nt < 4; nt++) {
                        mma4(sacc[mt][nt], fa[mt].x, fb[mt].x, fa[mt].z, fb[mt].z, gg[nt].x, gg[nt].z);
                        mma4(sacc[mt][nt], fa[mt].x, fb[mt].x, fa[mt].z, fb[mt].z, gg[nt].y, gg[nt].w);
                        mma4(sacc[mt][nt], fa[mt].y, fb[mt].y, fa[mt].w, fb[mt].w, gg[nt].x, gg[nt].z);
                    }
            }
        }

        // ---- online softmax ----
        float cmax[2][2];
#pragma unroll
        for (int mt = 0; mt < 2; mt++)
#pragma unroll
            for (int h = 0; h < 2; h++) {
                float m_ = -INFINITY;
#pragma unroll
                for (int nt = 0; nt < 4; nt++)
                    m_ = fmaxf(m_, fmaxf(sacc[mt][nt][2 * h], sacc[mt][nt][2 * h + 1]));
                m_ = fmaxf(m_, __shfl_xor_sync(0xffffffffu, m_, 1));
                m_ = fmaxf(m_, __shfl_xor_sync(0xffffffffu, m_, 2));
                cmax[mt][h] = m_;
            }
        if (tq == 0)
#pragma unroll
            for (int mt = 0; mt < 2; mt++)
#pragma unroll
                for (int h = 0; h < 2; h++)
                    red[wn][wm * 32 + mt * 16 + gq + 8 * h] = cmax[mt][h];
        __syncthreads();
        float nmax[2][2], fct[2][2];
#pragma unroll
        for (int mt = 0; mt < 2; mt++)
#pragma unroll
            for (int h = 0; h < 2; h++) {
                int rl = wm * 32 + mt * 16 + gq + 8 * h;
                float m_ = fmaxf(fmaxf(red[0][rl], red[1][rl]), fmaxf(red[2][rl], red[3][rl]));
                float nm = fmaxf(rmax[mt][h], m_);
                fct[mt][h] = __expf(rmax[mt][h] - nm);
                rmax[mt][h] = nm; nmax[mt][h] = nm;
            }
        float lsum[2][2] = {{0.f, 0.f}, {0.f, 0.f}};
        __syncthreads();
#pragma unroll
        for (int mt = 0; mt < 2; mt++) {
            int rl0 = wm * 32 + mt * 16 + gq;
#pragma unroll
            for (int nt = 0; nt < 4; nt++) {
                int col = wn * 32 + nt * 8 + 2 * tq;
                float e0 = __expf(sacc[mt][nt][0] - nmax[mt][0]);
                float e1 = __expf(sacc[mt][nt][1] - nmax[mt][0]);
                float e2 = __expf(sacc[mt][nt][2] - nmax[mt][1]);
                float e3 = __expf(sacc[mt][nt][3] - nmax[mt][1]);
                int g16 = col >> 4;
                int pc0 = (((col & 3) << 2) + (((col >> 3) & 1) << 1) + ((col >> 2) & 1));
                int c1 = col + 1;
                int pc1 = (((c1 & 3) << 2) + (((c1 >> 3) & 1) << 1) + ((c1 >> 2) & 1));
                Ps[((g16 * 64 + rl0) << 4) + pc0]     = f2tf(e0);
                Ps[((g16 * 64 + rl0) << 4) + pc1]     = f2tf(e1);
                Ps[((g16 * 64 + rl0 + 8) << 4) + pc0] = f2tf(e2);
                Ps[((g16 * 64 + rl0 + 8) << 4) + pc1] = f2tf(e3);
                lsum[mt][0] += e0 + e1; lsum[mt][1] += e2 + e3;
            }
        }
#pragma unroll
        for (int mt = 0; mt < 2; mt++)
#pragma unroll
            for (int h = 0; h < 2; h++) {
                lsum[mt][h] += __shfl_xor_sync(0xffffffffu, lsum[mt][h], 1);
                lsum[mt][h] += __shfl_xor_sync(0xffffffffu, lsum[mt][h], 2);
            }
        if (tq == 0)
#pragma unroll
            for (int mt = 0; mt < 2; mt++)
#pragma unroll
                for (int h = 0; h < 2; h++)
                    red[wn][wm * 32 + mt * 16 + gq + 8 * h] = lsum[mt][h];
        __syncthreads();
#pragma unroll
        for (int mt = 0; mt < 2; mt++)
#pragma unroll
            for (int h = 0; h < 2; h++) {
                int rl = wm * 32 + mt * 16 + gq + 8 * h;
                float cs = red[0][rl] + red[1][rl] + red[2][rl] + red[3][rl];
                rsum[mt][h] = rsum[mt][h] * fct[mt][h] + cs;
            }
#pragma unroll
        for (int mt = 0; mt < 2; mt++)
#pragma unroll
            for (int nt = 0; nt < 8; nt++) {
                oacc[mt][nt][0] *= fct[mt][0]; oacc[mt][nt][1] *= fct[mt][0];
                oacc[mt][nt][2] *= fct[mt][1]; oacc[mt][nt][3] *= fct[mt][1];
            }

        // ---- O += P @ G, G streamed in 32-row sub-chunks ----
        for (int ks = 0; ks < 4; ks++) {
            __syncthreads();
            {
                const uint4* src = (const uint4*)(g_gv_u + ((size_t)b * 64 + mc * 8 + ks * 2) * 4096);
                uint4* dst = (uint4*)U;
#pragma unroll
                for (int p = 0; p < 8; p++) dst[tid + p * 256] = src[tid + p * 256];
            }
            __syncthreads();
#pragma unroll
            for (int k16l = 0; k16l < 2; k16l++) {
                int ksg = ks * 2 + k16l;
                uint4 pa[2], pb[2], gg[8];
#pragma unroll
                for (int mt = 0; mt < 2; mt++) {
                    int rl0 = wm * 32 + mt * 16 + gq;
                    pa[mt] = *(const uint4*)(Ps + ((ksg * 64 + rl0) << 4) + (tq << 2));
                    pb[mt] = *(const uint4*)(Ps + ((ksg * 64 + rl0 + 8) << 4) + (tq << 2));
                }
#pragma unroll
                for (int nt = 0; nt < 8; nt++) {
                    int co = wn * 64 + nt * 8 + gq;
                    gg[nt] = *(const uint4*)(U + ((k16l * 256 + co) << 4) + (tq << 2));
                }
#pragma unroll
                for (int mt = 0; mt < 2; mt++)
#pragma unroll
                    for (int nt = 0; nt < 8; nt++) {
                        mma4(oacc[mt][nt], pa[mt].x, pb[mt].x, pa[mt].y, pb[mt].y, gg[nt].x, gg[nt].y);
                        mma4(oacc[mt][nt], pa[mt].z, pb[mt].z, pa[mt].w, pb[mt].w, gg[nt].z, gg[nt].w);
                    }
            }
        }
    }

    // ---- normalize + store ag in P16 fragment layout ----
    float inv[2][2];
#pragma unroll
    for (int mt = 0; mt < 2; mt++)
#pragma unroll
        for (int h = 0; h < 2; h++) inv[mt][h] = 1.0f / rsum[mt][h];
#pragma unroll
    for (int mt = 0; mt < 2; mt++) {
        int rl = wm * 32 + mt * 16 + gq;
        int p = p0 + rl, pt2 = p >> 7, rw = p & 127;
#pragma unroll
        for (int nt = 0; nt < 8; nt++) {
            int co = wn * 64 + nt * 8 + 2 * tq;
            int g16 = co >> 4;
            int pc0 = (((co & 3) << 2) + (((co >> 3) & 1) << 1) + ((co >> 2) & 1));
            int c1 = co + 1;
            int pc1 = (((c1 & 3) << 2) + (((c1 >> 3) & 1) << 1) + ((c1 >> 2) & 1));
            size_t base = (((size_t)b * 32 + pt2) * 16 + g16) * 2048;
            g_ag_u[base + ((rw) << 4) + pc0]     = f2tf(oacc[mt][nt][0] * inv[mt][0]);
            g_ag_u[base + ((rw) << 4) + pc1]     = f2tf(oacc[mt][nt][1] * inv[mt][0]);
            g_ag_u[base + ((rw + 8) << 4) + pc0] = f2tf(oacc[mt][nt][2] * inv[mt][1]);
            g_ag_u[base + ((rw + 8) << 4) + pc1] = f2tf(oacc[mt][nt][3] * inv[mt][1]);
        }
    }
}

// ---------------------------------------------------------------------------
// out: Y = x + sigma*(AG @ w_attn^T + b). M=128 pos, N=128 ch, K=256, plain tf32.
// ---------------------------------------------------------------------------
__global__ void __launch_bounds__(256, 2)
out_kernel(const float* __restrict__ x, const float* __restrict__ wA,
           const float* __restrict__ bA, const float* __restrict__ sigma,
           float* __restrict__ out)
{
    __shared__ unsigned As2[4096];   // [2][128][16]
    __shared__ unsigned Ws2[4096];
    const int tid = threadIdx.x, lane = tid & 31, wid = tid >> 5;
    const int gq = lane >> 2, tq = lane & 3;
    const int wm = wid & 1, wn = wid >> 1;
    const int b = blockIdx.z, p00 = blockIdx.x * 128, c00 = blockIdx.y * 128;

    float acc[4][4][4] = {};

    for (int k0 = 0; k0 < 256; k0 += 32) {
        __syncthreads();
        {
            const uint4* src = (const uint4*)(g_ag_u + (((size_t)b * 32 + (p00 >> 7)) * 16 + (k0 >> 4)) * 2048);
            uint4* dst = (uint4*)As2;
#pragma unroll
            for (int p = 0; p < 4; p++) dst[tid + p * 256] = src[tid + p * 256];
        }
#pragma unroll
        for (int p = 0; p < 4; p++) {
            int idx = tid + p * 256, r = idx >> 3, c4 = (idx & 7) << 2;
            float4 v = *(const float4*)(wA + (size_t)(c00 + r) * 256 + k0 + c4);
            unsigned* d = Ws2 + (((c4 >> 4) * 128 + r) << 4) + (((c4 >> 3) & 1) << 1) + ((c4 >> 2) & 1);
            d[0] = f2tf(v.x); d[4] = f2tf(v.y); d[8] = f2tf(v.z); d[12] = f2tf(v.w);
        }
        __syncthreads();
#pragma unroll
        for (int g16 = 0; g16 < 2; g16++) {
            uint4 fa[4], fb[4], gg[4];
#pragma unroll
            for (int mt = 0; mt < 4; mt++) {
                int r0 = wm * 64 + mt * 16 + gq;
                fa[mt] = *(const uint4*)(As2 + ((g16 * 128 + r0) << 4) + (tq << 2));
                fb[mt] = *(const uint4*)(As2 + ((g16 * 128 + r0 + 8) << 4) + (tq << 2));
            }
#pragma unroll
            for (int nt = 0; nt < 4; nt++) {
                int c0 = wn * 32 + nt * 8 + gq;
                gg[nt] = *(const uint4*)(Ws2 + ((g16 * 128 + c0) << 4) + (tq << 2));
            }
#pragma unroll
            for (int mt = 0; mt < 4; mt++)
#pragma unroll
                for (int nt = 0; nt < 4; nt++) {
                    mma4(acc[mt][nt], fa[mt].x, fb[mt].x, fa[mt].y, fb[mt].y, gg[nt].x, gg[nt].y);
                    mma4(acc[mt][nt], fa[mt].z, fb[mt].z, fa[mt].w, fb[mt].w, gg[nt].z, gg[nt].w);
                }
        }
    }

    const float sg = sigma[0];
#pragma unroll
    for (int mt = 0; mt < 4; mt++) {
        int p = p00 + wm * 64 + mt * 16 + gq;
#pragma unroll
        for (int nt = 0; nt < 4; nt++) {
            int c = c00 + wn * 32 + nt * 8 + 2 * tq;
            float bv0 = bA[c], bv1 = bA[c + 1];
            size_t i00 = ((size_t)b * 512 + c) * 4096 + p;
            out[i00]            = x[i00]            + sg * (acc[mt][nt][0] + bv0);
            out[i00 + 4096]     = x[i00 + 4096]     + sg * (acc[mt][nt][1] + bv1);
            out[i00 + 8]        = x[i00 + 8]        + sg * (acc[mt][nt][2] + bv0);
            out[i00 + 4096 + 8] = x[i00 + 4096 + 8] + sg * (acc[mt][nt][3] + bv1);
        }
    }
}

extern "C" void kernel_launch(void* const* d_in, const int* in_sizes, int n_in,
                              void* d_out, int out_size)
{
    const float* x       = (const float*)d_in[0];
    const float* w_theta = (const float*)d_in[1];
    const float* b_theta = (const float*)d_in[2];
    const float* w_phi   = (const float*)d_in[3];
    const float* b_phi   = (const float*)d_in[4];
    const float* w_g     = (const float*)d_in[5];
    const float* b_g     = (const float*)d_in[6];
    const float* w_attn  = (const float*)d_in[7];
    const float* b_attn  = (const float*)d_in[8];
    const float* sigma   = (const float*)d_in[9];
    float* out = (float*)d_out;

    static int init = 0;
    const int conv0_smem = 65536;
    const int conv1_smem = 33792;
    const int attn_smem  = 99328;
    if (!init) {
        cudaFuncSetAttribute(conv0_kernel, cudaFuncAttributeMaxDynamicSharedMemorySize, conv0_smem);
        cudaFuncSetAttribute(attn_kernel,  cudaFuncAttributeMaxDynamicSharedMemorySize, attn_smem);
        init = 1;
    }

    conv0_kernel<<<dim3(32, 1, NB), 256, conv0_smem>>>(x, w_theta, w_phi, b_theta, b_phi);
    conv1_kernel<<<dim3(32, 2, NB), 256, conv1_smem>>>(x, w_g, b_g);
    attn_kernel<<<dim3(64, NB), 256, attn_smem>>>();
    out_kernel<<<dim3(32, 4, NB), 256>>>(x, w_attn, b_attn, sigma, out);
}

// round 5
// speedup vs baseline: 1.3930x; 1.3930x over previous
#include <cuda_runtime.h>
#include <math.h>
#include <stdint.h>

// SAGAN SelfAttention: B=16, C=512, H=W=64, HW=4096, HW4=1024, C8=64, C2=256
#define NB 16

__device__ __align__(128) float g_theta[(size_t)NB * 4096 * 64];   // [b][p][c]
__device__ __align__(128) float g_phi  [(size_t)NB * 64 * 1024];   // [b][c][m]
__device__ __align__(128) float g_gv   [(size_t)NB * 1024 * 256];  // [b][m][co]
__device__ __align__(128) float g_ag   [(size_t)NB * 4096 * 256];  // [b][p][co]

__device__ __forceinline__ unsigned f2tf(float f) {
    unsigned r; asm("cvt.rna.tf32.f32 %0,%1;" : "=r"(r) : "f"(f)); return r;
}
__device__ __forceinline__ void tf32_split(float f, unsigned& hi, unsigned& lo) {
    asm("cvt.rna.tf32.f32 %0,%1;" : "=r"(hi) : "f"(f));
    float rem = f - __uint_as_float(hi);
    asm("cvt.rna.tf32.f32 %0,%1;" : "=r"(lo) : "f"(rem));
}
__device__ __forceinline__ void mma_tf32(float d[4], const unsigned a[4], const unsigned b[2]) {
    asm("mma.sync.aligned.m16n8k8.row.col.f32.tf32.tf32.f32 "
        "{%0,%1,%2,%3},{%4,%5,%6,%7},{%8,%9},{%0,%1,%2,%3};"
        : "+f"(d[0]), "+f"(d[1]), "+f"(d[2]), "+f"(d[3])
        : "r"(a[0]), "r"(a[1]), "r"(a[2]), "r"(a[3]), "r"(b[0]), "r"(b[1]));
}
__device__ __forceinline__ void cpa16(float* smem_dst, const float* gmem_src) {
    unsigned d = (unsigned)__cvta_generic_to_shared(smem_dst);
    asm volatile("cp.async.cg.shared.global [%0], [%1], 16;" :: "r"(d), "l"(gmem_src));
}
#define CP_COMMIT() asm volatile("cp.async.commit_group;")
#define CP_WAIT(n)  asm volatile("cp.async.wait_group %0;" :: "n"(n))

// ---------------------------------------------------------------------------
// Conv GEMM, 2-stage cp.async pipeline. A tile [128][44] (weights, row=out-ch),
// B tile [32][132] (x, row=k, col=128 positions = 2 image rows).
// EPI=0: theta rows 0-63 (transposed store) + phi rows 64-127 (pooled), 3xTF32.
// EPI=1: g (M=256 via grid.y), plain tf32, pooled.
// dyn smem: A0 A1 B0 B1 = (2*5632 + 2*4224)*4 = 78848 B; stage[128][66] aliases.
// ---------------------------------------------------------------------------
template <int EPI>
__global__ void __launch_bounds__(256, 2)
conv_kernel(const float* __restrict__ x,
            const float* __restrict__ wA, const float* __restrict__ wB,
            const float* __restrict__ bA, const float* __restrict__ bB)
{
    extern __shared__ float smf[];
    float* Ab[2] = { smf, smf + 5632 };
    float* Bb[2] = { smf + 11264, smf + 15488 };
    float (*stage)[66] = (float(*)[66])smf;

    const int tid = threadIdx.x, lane = tid & 31, wid = tid >> 5;
    const int gq = lane >> 2, tq = lane & 3;
    const int wm = wid & 1, wn = wid >> 1;
    const int b = blockIdx.z, tb = blockIdx.x;
    const int n0 = tb * 128, m0 = blockIdx.y * 128;
    const float* xb = x + ((size_t)b << 21);

    auto loadAB = [&](int buf, int k0) {
#pragma unroll
        for (int p = 0; p < 4; p++) {
            int idx = tid + p * 256, r = idx >> 3, c4 = (idx & 7) << 2;
            const float* wp = (EPI == 0)
                ? (r < 64 ? wA + (size_t)r * 512 : wB + (size_t)(r - 64) * 512)
                : (wA + (size_t)(m0 + r) * 512);
            cpa16(Ab[buf] + r * 44 + c4, wp + k0 + c4);
        }
#pragma unroll
        for (int p = 0; p < 4; p++) {
            int idx = tid + p * 256, r = idx >> 5, c4 = (idx & 31) << 2;
            cpa16(Bb[buf] + r * 132 + c4, xb + (size_t)(k0 + r) * 4096 + n0 + c4);
        }
        CP_COMMIT();
    };

    float acc[4][4][4] = {};
    loadAB(0, 0);
    int cur = 0;
    for (int it = 0; it < 16; it++) {
        if (it < 15) { loadAB(cur ^ 1, (it + 1) * 32); CP_WAIT(1); }
        else CP_WAIT(0);
        __syncthreads();
        const float* Af = Ab[cur];
        const float* Bf = Bb[cur];
#pragma unroll
        for (int k8 = 0; k8 < 4; k8++) {
            const int kk = k8 * 8;
            unsigned ahi[4][4], alo[4][4], bhi[4][2], blo[4][2];
#pragma unroll
            for (int mt = 0; mt < 4; mt++) {
                int r0 = wm * 64 + mt * 16 + gq;
                float a0 = Af[r0 * 44 + kk + tq],       a1 = Af[(r0 + 8) * 44 + kk + tq];
                float a2 = Af[r0 * 44 + kk + tq + 4],   a3 = Af[(r0 + 8) * 44 + kk + tq + 4];
                if constexpr (EPI == 0) {
                    tf32_split(a0, ahi[mt][0], alo[mt][0]); tf32_split(a1, ahi[mt][1], alo[mt][1]);
                    tf32_split(a2, ahi[mt][2], alo[mt][2]); tf32_split(a3, ahi[mt][3], alo[mt][3]);
                } else {
                    ahi[mt][0] = f2tf(a0); ahi[mt][1] = f2tf(a1);
                    ahi[mt][2] = f2tf(a2); ahi[mt][3] = f2tf(a3);
                }
            }
#pragma unroll
            for (int nt = 0; nt < 4; nt++) {
                int c0 = wn * 32 + nt * 8 + gq;
                float b0 = Bf[(kk + tq) * 132 + c0], b1 = Bf[(kk + tq + 4) * 132 + c0];
                if constexpr (EPI == 0) {
                    tf32_split(b0, bhi[nt][0], blo[nt][0]);
                    tf32_split(b1, bhi[nt][1], blo[nt][1]);
                } else {
                    bhi[nt][0] = f2tf(b0); bhi[nt][1] = f2tf(b1);
                }
            }
#pragma unroll
            for (int mt = 0; mt < 4; mt++)
#pragma unroll
                for (int nt = 0; nt < 4; nt++) {
                    mma_tf32(acc[mt][nt], ahi[mt], bhi[nt]);
                    if constexpr (EPI == 0) {
                        mma_tf32(acc[mt][nt], ahi[mt], blo[nt]);
                        mma_tf32(acc[mt][nt], alo[mt], bhi[nt]);
                    }
                }
        }
        __syncthreads();
        cur ^= 1;
    }

    // bias
#pragma unroll
    for (int mt = 0; mt < 4; mt++) {
        int R0 = m0 + wm * 64 + mt * 16 + gq, R1 = R0 + 8;
        float bv0 = (EPI == 0) ? (R0 < 64 ? bA[R0] : bB[R0 - 64]) : bA[R0];
        float bv1 = (EPI == 0) ? (R1 < 64 ? bA[R1] : bB[R1 - 64]) : bA[R1];
#pragma unroll
        for (int nt = 0; nt < 4; nt++) {
            acc[mt][nt][0] += bv0; acc[mt][nt][1] += bv0;
            acc[mt][nt][2] += bv1; acc[mt][nt][3] += bv1;
        }
    }

    if constexpr (EPI == 0) {
        if (wm == 0) {  // theta -> [b][p][c]
#pragma unroll
            for (int mt = 0; mt < 4; mt++) {
                int R0 = mt * 16 + gq;
#pragma unroll
                for (int nt = 0; nt < 4; nt++) {
                    int col = n0 + wn * 32 + nt * 8 + 2 * tq;
                    float* tp = g_theta + ((size_t)b * 4096 + col) * 64;
                    tp[R0] = acc[mt][nt][0];      tp[64 + R0] = acc[mt][nt][1];
                    tp[R0 + 8] = acc[mt][nt][2];  tp[64 + R0 + 8] = acc[mt][nt][3];
                }
            }
        } else {        // phi: w-pool in-register, stage for h-pool
#pragma unroll
            for (int mt = 0; mt < 4; mt++) {
                int r0 = 64 + mt * 16 + gq;
#pragma unroll
                for (int nt = 0; nt < 4; nt++) {
                    int j = wn * 16 + nt * 4 + tq;
                    stage[r0][j]     = fmaxf(acc[mt][nt][0], acc[mt][nt][1]);
                    stage[r0 + 8][j] = fmaxf(acc[mt][nt][2], acc[mt][nt][3]);
                }
            }
        }
        __syncthreads();
        for (int idx = tid; idx < 64 * 32; idx += 256) {
            int co = idx >> 5, wp = idx & 31;
            float v = fmaxf(stage[64 + co][wp], stage[64 + co][wp + 32]);
            g_phi[((size_t)b * 64 + co) * 1024 + tb * 32 + wp] = v;
        }
    } else {
#pragma unroll
        for (int mt = 0; mt < 4; mt++) {
            int r0 = wm * 64 + mt * 16 + gq;
#pragma unroll
            for (int nt = 0; nt < 4; nt++) {
                int j = wn * 16 + nt * 4 + tq;
                stage[r0][j]     = fmaxf(acc[mt][nt][0], acc[mt][nt][1]);
                stage[r0 + 8][j] = fmaxf(acc[mt][nt][2], acc[mt][nt][3]);
            }
        }
        __syncthreads();
        for (int idx = tid; idx < 128 * 32; idx += 256) {
            int wp = idx >> 7, r = idx & 127;
            float v = fmaxf(stage[r][wp], stage[r][wp + 32]);
            g_gv[((size_t)b * 1024 + tb * 32 + wp) * 256 + m0 + r] = v;
        }
    }
}

// ---------------------------------------------------------------------------
// Flash attention with cp.async. Block = (b, 64 query rows). 8 warps (2x4).
// S 64x128 3xTF32, online softmax, PV with G in 8x16-row chunks, 1-ahead
// prefetch ping-pong in the Ph/Gs union.
// dyn smem floats: Th[64][68]@0 | Ps[64][132]@4352 | U@12800 (Ph[64][132] or
// 2x Gs[16][260]) | red[4][64]@21248. Total 21504 f = 86016 B.
// ---------------------------------------------------------------------------
__global__ void __launch_bounds__(256)
attn_kernel()
{
    extern __shared__ float smf[];
    float* Th = smf;
    float* Ps = smf + 4352;
    float* U  = smf + 12800;
    float (*red)[64] = (float(*)[64])(smf + 21248);

    const int tid = threadIdx.x, lane = tid & 31, wid = tid >> 5;
    const int gq = lane >> 2, tq = lane & 3;
    const int wm = wid >> 2, wn = wid & 3;
    const int b = blockIdx.y, p0 = blockIdx.x * 64;

#pragma unroll
    for (int p = 0; p < 4; p++) {   // Th 64x64
        int idx = tid + p * 256, r = idx >> 4, c4 = (idx & 15) << 2;
        cpa16(Th + r * 68 + c4, g_theta + ((size_t)b * 4096 + p0 + r) * 64 + c4);
    }
    CP_COMMIT();

    float oacc[2][8][4] = {};
    float rmax[2][2] = {{-INFINITY, -INFINITY}, {-INFINITY, -INFINITY}};
    float rsum[2][2] = {{0.f, 0.f}, {0.f, 0.f}};

    for (int mc = 0; mc < 8; mc++) {
        const int mc0 = mc * 128;
        // ---- Ph load (U is free here: first iter trivially, later via PV's trailing sync)
#pragma unroll
        for (int p = 0; p < 8; p++) {
            int idx = tid + p * 256, r = idx >> 5, c4 = (idx & 31) << 2;
            cpa16(U + r * 132 + c4, g_phi + ((size_t)b * 64 + r) * 1024 + mc0 + c4);
        }
        CP_COMMIT(); CP_WAIT(0);
        __syncthreads();

        // ---- S = Th @ Ph (3xTF32, K=64) ----
        float sacc[2][4][4] = {};
#pragma unroll
        for (int k8 = 0; k8 < 8; k8++) {
            const int kk = k8 * 8;
            unsigned ahi[2][4], alo[2][4], bhi[4][2], blo[4][2];
#pragma unroll
            for (int mt = 0; mt < 2; mt++) {
                int r0 = wm * 32 + mt * 16 + gq;
                tf32_split(Th[r0 * 68 + kk + tq],           ahi[mt][0], alo[mt][0]);
                tf32_split(Th[(r0 + 8) * 68 + kk + tq],     ahi[mt][1], alo[mt][1]);
                tf32_split(Th[r0 * 68 + kk + tq + 4],       ahi[mt][2], alo[mt][2]);
                tf32_split(Th[(r0 + 8) * 68 + kk + tq + 4], ahi[mt][3], alo[mt][3]);
            }
#pragma unroll
            for (int nt = 0; nt < 4; nt++) {
                int c0 = wn * 32 + nt * 8 + gq;
                tf32_split(U[(kk + tq) * 132 + c0],     bhi[nt][0], blo[nt][0]);
                tf32_split(U[(kk + tq + 4) * 132 + c0], bhi[nt][1], blo[nt][1]);
            }
#pragma unroll
            for (int mt = 0; mt < 2; mt++)
#pragma unroll
                for (int nt = 0; nt < 4; nt++) {
                    mma_tf32(sacc[mt][nt], ahi[mt], bhi[nt]);
                    mma_tf32(sacc[mt][nt], ahi[mt], blo[nt]);
                    mma_tf32(sacc[mt][nt], alo[mt], bhi[nt]);
                }
        }

        // ---- online softmax ----
        float cmax[2][2];
#pragma unroll
        for (int mt = 0; mt < 2; mt++)
#pragma unroll
            for (int h = 0; h < 2; h++) {
                float m_ = -INFINITY;
#pragma unroll
                for (int nt = 0; nt < 4; nt++)
                    m_ = fmaxf(m_, fmaxf(sacc[mt][nt][2 * h], sacc[mt][nt][2 * h + 1]));
                m_ = fmaxf(m_, __shfl_xor_sync(0xffffffffu, m_, 1));
                m_ = fmaxf(m_, __shfl_xor_sync(0xffffffffu, m_, 2));
                cmax[mt][h] = m_;
            }
        if (tq == 0)
#pragma unroll
            for (int mt = 0; mt < 2; mt++)
#pragma unroll
                for (int h = 0; h < 2; h++)
                    red[wn][wm * 32 + mt * 16 + gq + 8 * h] = cmax[mt][h];
        __syncthreads();

        // prefetch G chunk 0 into U half 0 (Ph reads are done: S-mma finished)
        {
            const float* src = g_gv + ((size_t)b * 1024 + mc0) * 256;
#pragma unroll
            for (int p = 0; p < 4; p++) {
                int idx = tid + p * 256, r = idx >> 6, c4 = (idx & 63) << 2;
                cpa16(U + r * 260 + c4, src + r * 256 + c4);
            }
            CP_COMMIT();
        }

        float nmax[2][2], fct[2][2];
#pragma unroll
        for (int mt = 0; mt < 2; mt++)
#pragma unroll
            for (int h = 0; h < 2; h++) {
                int rl = wm * 32 + mt * 16 + gq + 8 * h;
                float m_ = fmaxf(fmaxf(red[0][rl], red[1][rl]), fmaxf(red[2][rl], red[3][rl]));
                float nm = fmaxf(rmax[mt][h], m_);
                fct[mt][h] = __expf(rmax[mt][h] - nm);
                rmax[mt][h] = nm; nmax[mt][h] = nm;
            }
        float lsum[2][2] = {{0.f, 0.f}, {0.f, 0.f}};
#pragma unroll
        for (int mt = 0; mt < 2; mt++) {
            int rl0 = wm * 32 + mt * 16 + gq;
#pragma unroll
            for (int nt = 0; nt < 4; nt++) {
                int col = wn * 32 + nt * 8 + 2 * tq;
                float e0 = __expf(sacc[mt][nt][0] - nmax[mt][0]);
                float e1 = __expf(sacc[mt][nt][1] - nmax[mt][0]);
                float e2 = __expf(sacc[mt][nt][2] - nmax[mt][1]);
                float e3 = __expf(sacc[mt][nt][3] - nmax[mt][1]);
                Ps[rl0 * 132 + col] = e0;       Ps[rl0 * 132 + col + 1] = e1;
                Ps[(rl0 + 8) * 132 + col] = e2; Ps[(rl0 + 8) * 132 + col + 1] = e3;
                lsum[mt][0] += e0 + e1; lsum[mt][1] += e2 + e3;
            }
        }
#pragma unroll
        for (int mt = 0; mt < 2; mt++)
#pragma unroll
            for (int h = 0; h < 2; h++) {
                lsum[mt][h] += __shfl_xor_sync(0xffffffffu, lsum[mt][h], 1);
                lsum[mt][h] += __shfl_xor_sync(0xffffffffu, lsum[mt][h], 2);
            }
        __syncthreads();
        if (tq == 0)
#pragma unroll
            for (int mt = 0; mt < 2; mt++)
#pragma unroll
                for (int h = 0; h < 2; h++)
                    red[wn][wm * 32 + mt * 16 + gq + 8 * h] = lsum[mt][h];
        __syncthreads();
#pragma unroll
        for (int mt = 0; mt < 2; mt++)
#pragma unroll
            for (int h = 0; h < 2; h++) {
                int rl = wm * 32 + mt * 16 + gq + 8 * h;
                float cs = red[0][rl] + red[1][rl] + red[2][rl] + red[3][rl];
                rsum[mt][h] = rsum[mt][h] * fct[mt][h] + cs;
            }
#pragma unroll
        for (int mt = 0; mt < 2; mt++)
#pragma unroll
            for (int nt = 0; nt < 8; nt++) {
                oacc[mt][nt][0] *= fct[mt][0]; oacc[mt][nt][1] *= fct[mt][0];
                oacc[mt][nt][2] *= fct[mt][1]; oacc[mt][nt][3] *= fct[mt][1];
            }

        // ---- O += P @ G, 8 chunks of 16 rows, 1-ahead prefetch ----
        for (int h = 0; h < 8; h++) {
            if (h < 7) {
                const float* src = g_gv + ((size_t)b * 1024 + mc0 + (h + 1) * 16) * 256;
                float* dsth = U + ((h + 1) & 1) * 4160;
#pragma unroll
                for (int p = 0; p < 4; p++) {
                    int idx = tid + p * 256, r = idx >> 6, c4 = (idx & 63) << 2;
                    cpa16(dsth + r * 260 + c4, src + r * 256 + c4);
                }
                CP_COMMIT(); CP_WAIT(1);
            } else CP_WAIT(0);
            __syncthreads();
            const float* Gh = U + (h & 1) * 4160;
#pragma unroll
            for (int k8i = 0; k8i < 2; k8i++) {
                const int kg = h * 16 + k8i * 8;
                unsigned af[2][4], bf[8][2];
#pragma unroll
                for (int mt = 0; mt < 2; mt++) {
                    int rl = wm * 32 + mt * 16 + gq;
                    af[mt][0] = f2tf(Ps[rl * 132 + kg + tq]);
                    af[mt][1] = f2tf(Ps[(rl + 8) * 132 + kg + tq]);
                    af[mt][2] = f2tf(Ps[rl * 132 + kg + tq + 4]);
                    af[mt][3] = f2tf(Ps[(rl + 8) * 132 + kg + tq + 4]);
                }
#pragma unroll
                for (int nt = 0; nt < 8; nt++) {
                    int co = wn * 64 + nt * 8 + gq;
                    bf[nt][0] = f2tf(Gh[(k8i * 8 + tq) * 260 + co]);
                    bf[nt][1] = f2tf(Gh[(k8i * 8 + tq + 4) * 260 + co]);
                }
#pragma unroll
                for (int mt = 0; mt < 2; mt++)
#pragma unroll
                    for (int nt = 0; nt < 8; nt++)
                        mma_tf32(oacc[mt][nt], af[mt], bf[nt]);
            }
            __syncthreads();
        }
    }

    float inv[2][2];
#pragma unroll
    for (int mt = 0; mt < 2; mt++)
#pragma unroll
        for (int h = 0; h < 2; h++) inv[mt][h] = 1.0f / rsum[mt][h];
#pragma unroll
    for (int mt = 0; mt < 2; mt++) {
        int rl = wm * 32 + mt * 16 + gq;
#pragma unroll
        for (int nt = 0; nt < 8; nt++) {
            int co = wn * 64 + nt * 8 + 2 * tq;
            float2 v0 = make_float2(oacc[mt][nt][0] * inv[mt][0], oacc[mt][nt][1] * inv[mt][0]);
            float2 v1 = make_float2(oacc[mt][nt][2] * inv[mt][1], oacc[mt][nt][3] * inv[mt][1]);
            *(float2*)(g_ag + ((size_t)b * 4096 + p0 + rl) * 256 + co) = v0;
            *(float2*)(g_ag + ((size_t)b * 4096 + p0 + rl + 8) * 256 + co) = v1;
        }
    }
}

// ---------------------------------------------------------------------------
// Final conv + residual, 2-stage pipeline. A [128 pos][44], W [128 ch][44],
// K=256, plain tf32. dyn smem = 4*5632*4 = 90112 B.
// ---------------------------------------------------------------------------
__global__ void __launch_bounds__(256, 2)
out_kernel(const float* __restrict__ x, const float* __restrict__ wA,
           const float* __restrict__ bA, const float* __restrict__ sigma,
           float* __restrict__ out)
{
    extern __shared__ float smf[];
    float* Ab[2] = { smf, smf + 5632 };
    float* Wb[2] = { smf + 11264, smf + 16896 };
    const int tid = threadIdx.x, lane = tid & 31, wid = tid >> 5;
    const int gq = lane >> 2, tq = lane & 3;
    const int wm = wid & 1, wn = wid >> 1;
    const int b = blockIdx.z, p00 = blockIdx.x * 128, c00 = blockIdx.y * 128;

    auto loadAW = [&](int buf, int k0) {
#pragma unroll
        for (int p = 0; p < 4; p++) {
            int idx = tid + p * 256, r = idx >> 3, c4 = (idx & 7) << 2;
            cpa16(Ab[buf] + r * 44 + c4, g_ag + ((size_t)b * 4096 + p00 + r) * 256 + k0 + c4);
            cpa16(Wb[buf] + r * 44 + c4, wA + (size_t)(c00 + r) * 256 + k0 + c4);
        }
        CP_COMMIT();
    };

    float acc[4][4][4] = {};
    loadAW(0, 0);
    int cur = 0;
    for (int it = 0; it < 8; it++) {
        if (it < 7) { loadAW(cur ^ 1, (it + 1) * 32); CP_WAIT(1); }
        else CP_WAIT(0);
        __syncthreads();
        const float* Af = Ab[cur];
        const float* Wf = Wb[cur];
#pragma unroll
        for (int k8 = 0; k8 < 4; k8++) {
            const int kk = k8 * 8;
            unsigned af[4][4], bf[4][2];
#pragma unroll
            for (int mt = 0; mt < 4; mt++) {
                int r0 = wm * 64 + mt * 16 + gq;
                af[mt][0] = f2tf(Af[r0 * 44 + kk + tq]);
                af[mt][1] = f2tf(Af[(r0 + 8) * 44 + kk + tq]);
                af[mt][2] = f2tf(Af[r0 * 44 + kk + tq + 4]);
                af[mt][3] = f2tf(Af[(r0 + 8) * 44 + kk + tq + 4]);
            }
#pragma unroll
            for (int nt = 0; nt < 4; nt++) {
                int c0 = wn * 32 + nt * 8 + gq;
                bf[nt][0] = f2tf(Wf[c0 * 44 + kk + tq]);
                bf[nt][1] = f2tf(Wf[c0 * 44 + kk + tq + 4]);
            }
#pragma unroll
            for (int mt = 0; mt < 4; mt++)
#pragma unroll
                for (int nt = 0; nt < 4; nt++)
                    mma_tf32(acc[mt][nt], af[mt], bf[nt]);
        }
        __syncthreads();
        cur ^= 1;
    }

    const float sg = sigma[0];
#pragma unroll
    for (int mt = 0; mt < 4; mt++) {
        int p = p00 + wm * 64 + mt * 16 + gq;
#pragma unroll
        for (int nt = 0; nt < 4; nt++) {
            int c = c00 + wn * 32 + nt * 8 + 2 * tq;
            float bv0 = bA[c], bv1 = bA[c + 1];
            size_t i00 = ((size_t)b * 512 + c) * 4096 + p;
            out[i00]            = x[i00]            + sg * (acc[mt][nt][0] + bv0);
            out[i00 + 4096]     = x[i00 + 4096]     + sg * (acc[mt][nt][1] + bv1);
            out[i00 + 8]        = x[i00 + 8]        + sg * (acc[mt][nt][2] + bv0);
            out[i00 + 4096 + 8] = x[i00 + 4096 + 8] + sg * (acc[mt][nt][3] + bv1);
        }
    }
}

extern "C" void kernel_launch(void* const* d_in, const int* in_sizes, int n_in,
                              void* d_out, int out_size)
{
    const float* x       = (const float*)d_in[0];
    const float* w_theta = (const float*)d_in[1];
    const float* b_theta = (const float*)d_in[2];
    const float* w_phi   = (const float*)d_in[3];
    const float* b_phi   = (const float*)d_in[4];
    const float* w_g     = (const float*)d_in[5];
    const float* b_g     = (const float*)d_in[6];
    const float* w_attn  = (const float*)d_in[7];
    const float* b_attn  = (const float*)d_in[8];
    const float* sigma   = (const float*)d_in[9];
    float* out = (float*)d_out;

    static int init = 0;
    const int conv_smem = 78848;
    const int attn_smem = 86016;
    const int out_smem  = 90112;
    if (!init) {
        cudaFuncSetAttribute(conv_kernel<0>, cudaFuncAttributeMaxDynamicSharedMemorySize, conv_smem);
        cudaFuncSetAttribute(conv_kernel<1>, cudaFuncAttributeMaxDynamicSharedMemorySize, conv_smem);
        cudaFuncSetAttribute(attn_kernel,    cudaFuncAttributeMaxDynamicSharedMemorySize, attn_smem);
        cudaFuncSetAttribute(out_kernel,     cudaFuncAttributeMaxDynamicSharedMemorySize, out_smem);
        init = 1;
    }

    conv_kernel<0><<<dim3(32, 1, NB), 256, conv_smem>>>(x, w_theta, w_phi, b_theta, b_phi);
    conv_kernel<1><<<dim3(32, 2, NB), 256, conv_smem>>>(x, w_g, nullptr, b_g, nullptr);
    attn_kernel<<<dim3(64, NB), 256, attn_smem>>>();
    out_kernel<<<dim3(32, 4, NB), 256, out_smem>>>(x, w_attn, b_attn, sigma, out);
}

// round 10
// speedup vs baseline: 1.9408x; 1.3932x over previous
#include <cuda_runtime.h>
#include <cuda_fp16.h>
#include <math.h>
#include <stdint.h>

#define NB 16
// half hi/lo planes
__device__ __align__(128) __half gx_h [(size_t)NB * 512 * 4096];
__device__ __align__(128) __half gx_l [(size_t)NB * 512 * 4096];
__device__ __align__(128) __half gwc_h[128 * 512], gwc_l[128 * 512];
__device__ __align__(128) __half gwg_h[256 * 512], gwg_l[256 * 512];
__device__ __align__(128) __half gwa_h[512 * 256], gwa_l[512 * 256];
__device__ __align__(128) __half gth_h[(size_t)NB * 4096 * 64], gth_l[(size_t)NB * 4096 * 64];
__device__ __align__(128) __half gph_h[(size_t)NB * 1024 * 64], gph_l[(size_t)NB * 1024 * 64];
__device__ __align__(128) __half ggv_h[(size_t)NB * 1024 * 256], ggv_l[(size_t)NB * 1024 * 256];
__device__ __align__(128) __half gag_h[(size_t)NB * 4096 * 256];

__device__ __forceinline__ void fsplit(float v, __half& h, __half& l) {
    h = __float2half_rn(v); l = __float2half_rn(v - __half2float(h));
}
__device__ __forceinline__ uint4 ldmx4(unsigned a) {
    uint4 r;
    asm volatile("ldmatrix.sync.aligned.m8n8.x4.shared.b16 {%0,%1,%2,%3},[%4];"
        : "=r"(r.x), "=r"(r.y), "=r"(r.z), "=r"(r.w) : "r"(a));
    return r;
}
__device__ __forceinline__ uint4 ldmx4t(unsigned a) {
    uint4 r;
    asm volatile("ldmatrix.sync.aligned.m8n8.x4.trans.shared.b16 {%0,%1,%2,%3},[%4];"
        : "=r"(r.x), "=r"(r.y), "=r"(r.z), "=r"(r.w) : "r"(a));
    return r;
}
__device__ __forceinline__ void hmma(float d[4], const uint4& a, unsigned b0, unsigned b1) {
    asm("mma.sync.aligned.m16n8k16.row.col.f32.f16.f16.f32 "
        "{%0,%1,%2,%3},{%4,%5,%6,%7},{%8,%9},{%0,%1,%2,%3};"
        : "+f"(d[0]), "+f"(d[1]), "+f"(d[2]), "+f"(d[3])
        : "r"(a.x), "r"(a.y), "r"(a.z), "r"(a.w), "r"(b0), "r"(b1));
}
__device__ __forceinline__ void cph16(unsigned dst, const __half* src) {
    asm volatile("cp.async.cg.shared.global [%0], [%1], 16;" :: "r"(dst), "l"(src));
}
#define CP_COMMIT() asm volatile("cp.async.commit_group;")
#define CP_WAIT(n)  asm volatile("cp.async.wait_group %0;" :: "n"(n))

__global__ void __launch_bounds__(256) prep_x(const float* __restrict__ x) {
    size_t i = ((size_t)blockIdx.x * 256 + threadIdx.x) * 4;
    float4 v = *(const float4*)(x + i);
    __half h0,l0,h1,l1,h2,l2,h3,l3;
    fsplit(v.x,h0,l0); fsplit(v.y,h1,l1); fsplit(v.z,h2,l2); fsplit(v.w,h3,l3);
    ((__half2*)(gx_h+i))[0] = __halves2half2(h0,h1); ((__half2*)(gx_h+i))[1] = __halves2half2(h2,h3);
    ((__half2*)(gx_l+i))[0] = __halves2half2(l0,l1); ((__half2*)(gx_l+i))[1] = __halves2half2(l2,l3);
}
__global__ void __launch_bounds__(256)
prep_w(const float* __restrict__ wT, const float* __restrict__ wP,
       const float* __restrict__ wG, const float* __restrict__ wA) {
    int i4 = (blockIdx.x * 256 + threadIdx.x) * 4;
    const float* src; __half* dh; __half* dl;
    if (i4 < 65536)       { src = (i4 < 32768) ? wT + i4 : wP + (i4 - 32768); dh = gwc_h + i4; dl = gwc_l + i4; }
    else if (i4 < 196608) { int o = i4 - 65536;  src = wG + o; dh = gwg_h + o; dl = gwg_l + o; }
    else                  { int o = i4 - 196608; src = wA + o; dh = gwa_h + o; dl = gwa_l + o; }
    float4 v = *(const float4*)src;
    __half h0,l0,h1,l1,h2,l2,h3,l3;
    fsplit(v.x,h0,l0); fsplit(v.y,h1,l1); fsplit(v.z,h2,l2); fsplit(v.w,h3,l3);
    ((__half2*)dh)[0] = __halves2half2(h0,h1); ((__half2*)dh)[1] = __halves2half2(h2,h3);
    ((__half2*)dl)[0] = __halves2half2(l0,l1); ((__half2*)dl)[1] = __halves2half2(l2,l3);
}

// conv<0>=theta+phi (3-term), conv<1>=g (2-term). M128xN128, kstep 32, 2-stage.
// smem B: AH[2]@0(10240ea) AL[2]@20480 BH[2]@40960(8704ea) [BL[2]@58368 MODE0]
template <int MODE>
__global__ void __launch_bounds__(256, 2)
conv_fp16(const float* __restrict__ bA, const float* __restrict__ bB)
{
    extern __shared__ __half smh[];
    const int tid = threadIdx.x, lane = tid & 31, wid = tid >> 5;
    const int gq = lane >> 2, tq = lane & 3;
    const int wm = wid & 1, wn = wid >> 1;
    const int b = blockIdx.z, tb = blockIdx.x, m0 = blockIdx.y * 128;
    const int n0 = tb * 128;
    unsigned sb = (unsigned)__cvta_generic_to_shared(smh);
    const __half* wsh = MODE ? gwg_h : gwc_h;
    const __half* wsl = MODE ? gwg_l : gwc_l;
    const __half* xh = gx_h + ((size_t)b << 21);
    const __half* xl = gx_l + ((size_t)b << 21);
    float (*stage)[66] = (float(*)[66])smh;

    auto loadbuf = [&](int buf, int k0) {
#pragma unroll
        for (int i = 0; i < 4; i++) {
            int idx = tid + i * 256, pl = idx >> 9, rem = idx & 511;
            int r = rem >> 2, c8 = rem & 3;
            const __half* src = (pl ? wsl : wsh) + (size_t)(m0 + r) * 512 + k0 + c8 * 8;
            cph16(sb + (unsigned)pl * 20480u + (unsigned)buf * 10240u + r * 80u + c8 * 16u, src);
        }
#pragma unroll
        for (int i = 0; i < (MODE ? 2 : 4); i++) {
            int idx = tid + i * 256, pl = idx >> 9, rem = idx & 511;
            int r = rem >> 4, c8 = rem & 15;
            const __half* src = (pl ? xl : xh) + (size_t)(k0 + r) * 4096 + n0 + c8 * 8;
            cph16(sb + 40960u + (unsigned)pl * 17408u + (unsigned)buf * 8704u + r * 272u + c8 * 16u, src);
        }
        CP_COMMIT();
    };

    float acc[4][4][4] = {};
    loadbuf(0, 0);
    for (int it = 0; it < 16; it++) {
        int buf = it & 1;
        if (it < 15) { loadbuf(buf ^ 1, (it + 1) * 32); CP_WAIT(1); } else CP_WAIT(0);
        __syncthreads();
        unsigned Ah = sb + (unsigned)buf * 10240u, Al = Ah + 20480u;
        unsigned Bh = sb + 40960u + (unsigned)buf * 8704u, Bl = Bh + 17408u;
#pragma unroll
        for (int k16 = 0; k16 < 2; k16++) {
            const int kk = k16 * 16;
            uint4 bh[2], bl[2];
            unsigned krow = kk + (lane & 7) + ((lane >> 3) & 1) * 8;
            unsigned nc0 = wn * 32 + ((lane >> 4) & 1) * 8;
#pragma unroll
            for (int ng = 0; ng < 2; ng++) {
                unsigned off = krow * 272u + (nc0 + ng * 16) * 2u;
                bh[ng] = ldmx4t(Bh + off);
                if (MODE == 0) bl[ng] = ldmx4t(Bl + off);
            }
#pragma unroll
            for (int mg = 0; mg < 4; mg++) {
                unsigned aoff = (wm * 64 + mg * 16 + (lane & 15)) * 80u + (kk + (lane >> 4) * 8) * 2u;
                uint4 ah = ldmx4(Ah + aoff);
                uint4 al = ldmx4(Al + aoff);
#pragma unroll
                for (int ng = 0; ng < 2; ng++) {
                    hmma(acc[mg][ng * 2 + 0], ah, bh[ng].x, bh[ng].y);
                    hmma(acc[mg][ng * 2 + 1], ah, bh[ng].z, bh[ng].w);
                    hmma(acc[mg][ng * 2 + 0], al, bh[ng].x, bh[ng].y);
                    hmma(acc[mg][ng * 2 + 1], al, bh[ng].z, bh[ng].w);
                    if (MODE == 0) {
                        hmma(acc[mg][ng * 2 + 0], ah, bl[ng].x, bl[ng].y);
                        hmma(acc[mg][ng * 2 + 1], ah, bl[ng].z, bl[ng].w);
                    }
                }
            }
        }
        __syncthreads();
    }

#pragma unroll
    for (int mt = 0; mt < 4; mt++) {
        int R0 = m0 + wm * 64 + mt * 16 + gq, R1 = R0 + 8;
        float bv0 = (MODE == 0) ? (R0 < 64 ? bA[R0] : bB[R0 - 64]) : bA[R0];
        float bv1 = (MODE == 0) ? (R1 < 64 ? bA[R1] : bB[R1 - 64]) : bA[R1];
#pragma unroll
        for (int nt = 0; nt < 4; nt++) {
            acc[mt][nt][0] += bv0; acc[mt][nt][1] += bv0;
            acc[mt][nt][2] += bv1; acc[mt][nt][3] += bv1;
        }
    }

    if constexpr (MODE == 0) {
        if (wm == 0) {
#pragma unroll
            for (int mt = 0; mt < 4; mt++) {
                int R0 = mt * 16 + gq;
#pragma unroll
                for (int nt = 0; nt < 4; nt++) {
                    int col = n0 + wn * 32 + nt * 8 + 2 * tq;
                    size_t base = ((size_t)b * 4096 + col) * 64;
                    __half h, l;
                    fsplit(acc[mt][nt][0], h, l); gth_h[base + R0] = h;          gth_l[base + R0] = l;
                    fsplit(acc[mt][nt][1], h, l); gth_h[base + 64 + R0] = h;     gth_l[base + 64 + R0] = l;
                    fsplit(acc[mt][nt][2], h, l); gth_h[base + R0 + 8] = h;      gth_l[base + R0 + 8] = l;
                    fsplit(acc[mt][nt][3], h, l); gth_h[base + 64 + R0 + 8] = h; gth_l[base + 64 + R0 + 8] = l;
                }
            }
        } else {
#pragma unroll
            for (int mt = 0; mt < 4; mt++) {
                int r0 = 64 + mt * 16 + gq;
#pragma unroll
                for (int nt = 0; nt < 4; nt++) {
                    int j = wn * 16 + nt * 4 + tq;
                    stage[r0][j]     = fmaxf(acc[mt][nt][0], acc[mt][nt][1]);
                    stage[r0 + 8][j] = fmaxf(acc[mt][nt][2], acc[mt][nt][3]);
                }
            }
        }
        __syncthreads();
        for (int idx = tid; idx < 64 * 32; idx += 256) {
            int co = idx >> 5, wp = idx & 31;
            float v = fmaxf(stage[64 + co][wp], stage[64 + co][wp + 32]);
            size_t o = ((size_t)b * 1024 + tb * 32 + wp) * 64 + co;
            __half h, l; fsplit(v, h, l);
            gph_h[o] = h; gph_l[o] = l;
        }
    } else {
#pragma unroll
        for (int mt = 0; mt < 4; mt++) {
            int r0 = wm * 64 + mt * 16 + gq;
#pragma unroll
            for (int nt = 0; nt < 4; nt++) {
                int j = wn * 16 + nt * 4 + tq;
                stage[r0][j]     = fmaxf(acc[mt][nt][0], acc[mt][nt][1]);
                stage[r0 + 8][j] = fmaxf(acc[mt][nt][2], acc[mt][nt][3]);
            }
        }
        __syncthreads();
        for (int idx = tid; idx < 128 * 32; idx += 256) {
            int wp = idx >> 7, r = idx & 127;
            float v = fmaxf(stage[r][wp], stage[r][wp + 32]);
            size_t o = ((size_t)b * 1024 + tb * 32 + wp) * 256 + m0 + r;
            __half h, l; fsplit(v, h, l);
            ggv_h[o] = h; ggv_l[o] = l;
        }
    }
}

// attn: 64 q-rows/block, warps 2m x 4n. S 3-term; PV 2-term, G 16-row chunks.
// bytes: ThH@0(9216) ThL@9216 Ps@18432(17408) U@35840 (PhH 18432, PhL@54272 |
//        Gbuf: 35840+buf*16896+pl*8448) red@72704. total 73728.
__global__ void __launch_bounds__(256)
attn_fp16()
{
    extern __shared__ __half smh[];
    const int tid = threadIdx.x, lane = tid & 31, wid = tid >> 5;
    const int gq = lane >> 2, tq = lane & 3;
    const int wm = wid >> 2, wn = wid & 3;
    const int b = blockIdx.y, p0 = blockIdx.x * 64;
    unsigned sb = (unsigned)__cvta_generic_to_shared(smh);
    __half* Psp = smh + 9216;
    float (*red)[64] = (float(*)[64])((char*)smh + 72704);

#pragma unroll
    for (int i = 0; i < 4; i++) {
        int idx = tid + i * 256, pl = idx >> 9, r = (idx >> 3) & 63, c8 = idx & 7;
        const __half* src = (pl ? gth_l : gth_h) + ((size_t)b * 4096 + p0 + r) * 64 + c8 * 8;
        cph16(sb + (unsigned)pl * 9216u + r * 144u + c8 * 16u, src);
    }
    CP_COMMIT();

    float oacc[2][8][4] = {};
    float rmax[2][2] = {{-INFINITY, -INFINITY}, {-INFINITY, -INFINITY}};
    float rsum[2][2] = {{0.f, 0.f}, {0.f, 0.f}};

    auto loadG = [&](int buf, int mc0, int hh) {
#pragma unroll
        for (int i = 0; i < 4; i++) {
            int idx = tid + i * 256, pl = idx >> 9, r = (idx >> 5) & 15, c8 = idx & 31;
            const __half* src = (pl ? ggv_l : ggv_h) + ((size_t)b * 1024 + mc0 + hh * 16 + r) * 256 + c8 * 8;
            cph16(sb + 35840u + (unsigned)buf * 16896u + (unsigned)pl * 8448u + r * 528u + c8 * 16u, src);
        }
        CP_COMMIT();
    };

    for (int mc = 0; mc < 8; mc++) {
        const int mc0 = mc * 128;
#pragma unroll
        for (int i = 0; i < 8; i++) {
            int idx = tid + i * 256, pl = idx >> 10, r = (idx >> 3) & 127, c8 = idx & 7;
            const __half* src = (pl ? gph_l : gph_h) + ((size_t)b * 1024 + mc0 + r) * 64 + c8 * 8;
            cph16(sb + 35840u + (unsigned)pl * 18432u + r * 144u + c8 * 16u, src);
        }
        CP_COMMIT(); CP_WAIT(0);
        __syncthreads();

        float sacc[2][4][4] = {};
        const unsigned ThH = sb, ThL = sb + 9216u;
        const unsigned PhH = sb + 35840u, PhL = PhH + 18432u;
#pragma unroll
        for (int k16 = 0; k16 < 4; k16++) {
            const int kk = k16 * 16;
            uint4 bh[2], bl[2];
            unsigned nrow = wn * 32 + (lane & 7) + ((lane >> 4) & 1) * 8;
            unsigned kc = kk + ((lane >> 3) & 1) * 8;
#pragma unroll
            for (int ng = 0; ng < 2; ng++) {
                unsigned off = (nrow + ng * 16) * 144u + kc * 2u;
                bh[ng] = ldmx4(PhH + off);
                bl[ng] = ldmx4(PhL + off);
            }
#pragma unroll
            for (int mg = 0; mg < 2; mg++) {
                unsigned aoff = (wm * 32 + mg * 16 + (lane & 15)) * 144u + (kk + (lane >> 4) * 8) * 2u;
                uint4 ah = ldmx4(ThH + aoff);
                uint4 al = ldmx4(ThL + aoff);
#pragma unroll
                for (int ng = 0; ng < 2; ng++) {
                    hmma(sacc[mg][ng * 2 + 0], ah, bh[ng].x, bh[ng].y);
                    hmma(sacc[mg][ng * 2 + 1], ah, bh[ng].z, bh[ng].w);
                    hmma(sacc[mg][ng * 2 + 0], ah, bl[ng].x, bl[ng].y);
                    hmma(sacc[mg][ng * 2 + 1], ah, bl[ng].z, bl[ng].w);
                    hmma(sacc[mg][ng * 2 + 0], al, bh[ng].x, bh[ng].y);
                    hmma(sacc[mg][ng * 2 + 1], al, bh[ng].z, bh[ng].w);
                }
            }
        }

        float cmax[2][2];
#pragma unroll
        for (int mt = 0; mt < 2; mt++)
#pragma unroll
            for (int h = 0; h < 2; h++) {
                float m_ = -INFINITY;
#pragma unroll
                for (int nt = 0; nt < 4; nt++)
                    m_ = fmaxf(m_, fmaxf(sacc[mt][nt][2 * h], sacc[mt][nt][2 * h + 1]));
                m_ = fmaxf(m_, __shfl_xor_sync(0xffffffffu, m_, 1));
                m_ = fmaxf(m_, __shfl_xor_sync(0xffffffffu, m_, 2));
                cmax[mt][h] = m_;
            }
        if (tq == 0)
#pragma unroll
            for (int mt = 0; mt < 2; mt++)
#pragma unroll
                for (int h = 0; h < 2; h++)
                    red[wn][wm * 32 + mt * 16 + gq + 8 * h] = cmax[mt][h];
        __syncthreads();
        loadG(0, mc0, 0);

        float nmax[2][2], fct[2][2];
#pragma unroll
        for (int mt = 0; mt < 2; mt++)
#pragma unroll
            for (int h = 0; h < 2; h++) {
                int rl = wm * 32 + mt * 16 + gq + 8 * h;
                float m_ = fmaxf(fmaxf(red[0][rl], red[1][rl]), fmaxf(red[2][rl], red[3][rl]));
                float nm = fmaxf(rmax[mt][h], m_);
                fct[mt][h] = __expf(rmax[mt][h] - nm);
                rmax[mt][h] = nm; nmax[mt][h] = nm;
            }
        float lsum[2][2] = {{0.f, 0.f}, {0.f, 0.f}};
#pragma unroll
        for (int mt = 0; mt < 2; mt++) {
            int rl0 = wm * 32 + mt * 16 + gq;
#pragma unroll
            for (int nt = 0; nt < 4; nt++) {
                int col = wn * 32 + nt * 8 + 2 * tq;
                float e0 = __expf(sacc[mt][nt][0] - nmax[mt][0]);
                float e1 = __expf(sacc[mt][nt][1] - nmax[mt][0]);
                float e2 = __expf(sacc[mt][nt][2] - nmax[mt][1]);
                float e3 = __expf(sacc[mt][nt][3] - nmax[mt][1]);
                *(__half2*)(Psp + rl0 * 136 + col) = __floats2half2_rn(e0, e1);
                *(__half2*)(Psp + (rl0 + 8) * 136 + col) = __floats2half2_rn(e2, e3);
                lsum[mt][0] += e0 + e1; lsum[mt][1] += e2 + e3;
            }
        }
#pragma unroll
        for (int mt = 0; mt < 2; mt++)
#pragma unroll
            for (int h = 0; h < 2; h++) {
                lsum[mt][h] += __shfl_xor_sync(0xffffffffu, lsum[mt][h], 1);
                lsum[mt][h] += __shfl_xor_sync(0xffffffffu, lsum[mt][h], 2);
            }
        __syncthreads();
        if (tq == 0)
#pragma unroll
            for (int mt = 0; mt < 2; mt++)
#pragma unroll
                for (int h = 0; h < 2; h++)
                    red[wn][wm * 32 + mt * 16 + gq + 8 * h] = lsum[mt][h];
        __syncthreads();
#pragma unroll
        for (int mt = 0; mt < 2; mt++)
#pragma unroll
            for (int h = 0; h < 2; h++) {
                int rl = wm * 32 + mt * 16 + gq + 8 * h;
                float cs = red[0][rl] + red[1][rl] + red[2][rl] + red[3][rl];
                rsum[mt][h] = rsum[mt][h] * fct[mt][h] + cs;
            }
#pragma unroll
        for (int mt = 0; mt < 2; mt++)
#pragma unroll
            for (int nt = 0; nt < 8; nt++) {
                oacc[mt][nt][0] *= fct[mt][0]; oacc[mt][nt][1] *= fct[mt][0];
                oacc[mt][nt][2] *= fct[mt][1]; oacc[mt][nt][3] *= fct[mt][1];
            }

        for (int h = 0; h < 8; h++) {
            if (h < 7) { loadG((h + 1) & 1, mc0, h + 1); CP_WAIT(1); } else CP_WAIT(0);
            __syncthreads();
            unsigned GH = sb + 35840u + (unsigned)(h & 1) * 16896u, GL = GH + 8448u;
            uint4 gh[4], gl[4];
            unsigned krow = (lane & 7) + ((lane >> 3) & 1) * 8;
            unsigned nc0 = wn * 64 + ((lane >> 4) & 1) * 8;
#pragma unroll
            for (int ng = 0; ng < 4; ng++) {
                unsigned off = krow * 528u + (nc0 + ng * 16) * 2u;
                gh[ng] = ldmx4t(GH + off);
                gl[ng] = ldmx4t(GL + off);
            }
#pragma unroll
            for (int mg = 0; mg < 2; mg++) {
                unsigned aoff = sb + 18432u + (wm * 32 + mg * 16 + (lane & 15)) * 272u
                              + (h * 16 + (lane >> 4) * 8) * 2u;
                uint4 pa = ldmx4(aoff);
#pragma unroll
                for (int ng = 0; ng < 4; ng++) {
                    hmma(oacc[mg][ng * 2 + 0], pa, gh[ng].x, gh[ng].y);
                    hmma(oacc[mg][ng * 2 + 1], pa, gh[ng].z, gh[ng].w);
                    hmma(oacc[mg][ng * 2 + 0], pa, gl[ng].x, gl[ng].y);
                    hmma(oacc[mg][ng * 2 + 1], pa, gl[ng].z, gl[ng].w);
                }
            }
            __syncthreads();
        }
    }

    float inv[2][2];
#pragma unroll
    for (int mt = 0; mt < 2; mt++)
#pragma unroll
        for (int h = 0; h < 2; h++) inv[mt][h] = 1.0f / rsum[mt][h];
#pragma unroll
    for (int mt = 0; mt < 2; mt++) {
        int rl = wm * 32 + mt * 16 + gq;
#pragma unroll
        for (int nt = 0; nt < 8; nt++) {
            int co = wn * 64 + nt * 8 + 2 * tq;
            size_t o0 = ((size_t)b * 4096 + p0 + rl) * 256 + co;
            size_t o1 = o0 + 8 * 256;
            *(__half2*)(gag_h + o0) = __floats2half2_rn(oacc[mt][nt][0] * inv[mt][0], oacc[mt][nt][1] * inv[mt][0]);
            *(__half2*)(gag_h + o1) = __floats2half2_rn(oacc[mt][nt][2] * inv[mt][1], oacc[mt][nt][3] * inv[mt][1]);
        }
    }
}

// out: Y = x + sg*(AG @ wA^T + b). M128 pos x N128 ch, K=256, 2-term on W.
// bytes: A[2]@0(10240ea) WH[2]@20480 WL[2]@40960. total 61440.
__global__ void __launch_bounds__(256, 2)
out_fp16(const float* __restrict__ x, const float* __restrict__ bA,
         const float* __restrict__ sigma, float* __restrict__ out)
{
    extern __shared__ __half smh[];
    const int tid = threadIdx.x, lane = tid & 31, wid = tid >> 5;
    const int gq = lane >> 2, tq = lane & 3;
    const int wm = wid & 1, wn = wid >> 1;
    const int b = blockIdx.z, p00 = blockIdx.x * 128, c00 = blockIdx.y * 128;
    unsigned sb = (unsigned)__cvta_generic_to_shared(smh);

    auto loadbuf = [&](int buf, int k0) {
#pragma unroll
        for (int i = 0; i < 2; i++) {
            int idx = tid + i * 256, r = idx >> 2, c8 = idx & 3;
            cph16(sb + (unsigned)buf * 10240u + r * 80u + c8 * 16u,
                  gag_h + ((size_t)b * 4096 + p00 + r) * 256 + k0 + c8 * 8);
        }
#pragma unroll
        for (int i = 0; i < 4; i++) {
            int idx = tid + i * 256, pl = idx >> 9, rem = idx & 511;
            int r = rem >> 2, c8 = rem & 3;
            const __half* src = (pl ? gwa_l : gwa_h) + (size_t)(c00 + r) * 256 + k0 + c8 * 8;
            cph16(sb + 20480u + (unsigned)pl * 20480u + (unsigned)buf * 10240u + r * 80u + c8 * 16u, src);
        }
        CP_COMMIT();
    };

    float acc[4][4][4] = {};
    loadbuf(0, 0);
    for (int it = 0; it < 8; it++) {
        int buf = it & 1;
        if (it < 7) { loadbuf(buf ^ 1, (it + 1) * 32); CP_WAIT(1); } else CP_WAIT(0);
        __syncthreads();
        unsigned Ab = sb + (unsigned)buf * 10240u;
        unsigned Wh = sb + 20480u + (unsigned)buf * 10240u, Wl = Wh + 20480u;
#pragma unroll
        for (int k16 = 0; k16 < 2; k16++) {
            const int kk = k16 * 16;
            uint4 bh[2], bl[2];
            unsigned nrow = wn * 32 + (lane & 7) + ((lane >> 4) & 1) * 8;
            unsigned kc = kk + ((lane >> 3) & 1) * 8;
#pragma unroll
            for (int ng = 0; ng < 2; ng++) {
                unsigned off = (nrow + ng * 16) * 80u + kc * 2u;
                bh[ng] = ldmx4(Wh + off);
                bl[ng] = ldmx4(Wl + off);
            }
#pragma unroll
            for (int mg = 0; mg < 4; mg++) {
                unsigned aoff = (wm * 64 + mg * 16 + (lane & 15)) * 80u + (kk + (lane >> 4) * 8) * 2u;
                uint4 pa = ldmx4(Ab + aoff);
#pragma unroll
                for (int ng = 0; ng < 2; ng++) {
                    hmma(acc[mg][ng * 2 + 0], pa, bh[ng].x, bh[ng].y);
                    hmma(acc[mg][ng * 2 + 1], pa, bh[ng].z, bh[ng].w);
                    hmma(acc[mg][ng * 2 + 0], pa, bl[ng].x, bl[ng].y);
                    hmma(acc[mg][ng * 2 + 1], pa, bl[ng].z, bl[ng].w);
                }
            }
        }
        __syncthreads();
    }

    const float sg = sigma[0];
#pragma unroll
    for (int mt = 0; mt < 4; mt++) {
        int p = p00 + wm * 64 + mt * 16 + gq;
#pragma unroll
        for (int nt = 0; nt < 4; nt++) {
            int c = c00 + wn * 32 + nt * 8 + 2 * tq;
            float bv0 = bA[c], bv1 = bA[c + 1];
            size_t i00 = ((size_t)b * 512 + c) * 4096 + p;
            out[i00]            = x[i00]            + sg * (acc[mt][nt][0] + bv0);
            out[i00 + 4096]     = x[i00 + 4096]     + sg * (acc[mt][nt][1] + bv1);
            out[i00 + 8]        = x[i00 + 8]        + sg * (acc[mt][nt][2] + bv0);
            out[i00 + 4096 + 8] = x[i00 + 4096 + 8] + sg * (acc[mt][nt][3] + bv1);
        }
    }
}

extern "C" void kernel_launch(void* const* d_in, const int* in_sizes, int n_in,
                              void* d_out, int out_size)
{
    const float* x       = (const float*)d_in[0];
    const float* w_theta = (const float*)d_in[1];
    const float* b_theta = (const float*)d_in[2];
    const float* w_phi   = (const float*)d_in[3];
    const float* b_phi   = (const float*)d_in[4];
    const float* w_g     = (const float*)d_in[5];
    const float* b_g     = (const float*)d_in[6];
    const float* w_attn  = (const float*)d_in[7];
    const float* b_attn  = (const float*)d_in[8];
    const float* sigma   = (const float*)d_in[9];
    float* out = (float*)d_out;

    static int init = 0;
    const int conv0_smem = 75776, conv1_smem = 58368, attn_smem = 73728, out_smem = 61440;
    if (!init) {
        cudaFuncSetAttribute(conv_fp16<0>, cudaFuncAttributeMaxDynamicSharedMemorySize, conv0_smem);
        cudaFuncSetAttribute(conv_fp16<1>, cudaFuncAttributeMaxDynamicSharedMemorySize, conv1_smem);
        cudaFuncSetAttribute(attn_fp16,    cudaFuncAttributeMaxDynamicSharedMemorySize, attn_smem);
        cudaFuncSetAttribute(out_fp16,     cudaFuncAttributeMaxDynamicSharedMemorySize, out_smem);
        init = 1;
    }

    prep_x<<<32768, 256>>>(x);
    prep_w<<<320, 256>>>(w_theta, w_phi, w_g, w_attn);
    conv_fp16<0><<<dim3(32, 1, NB), 256, conv0_smem>>>(b_theta, b_phi);
    conv_fp16<1><<<dim3(32, 2, NB), 256, conv1_smem>>>(b_g, nullptr);
    attn_fp16<<<dim3(64, NB), 256, attn_smem>>>();
    out_fp16<<<dim3(32, 4, NB), 256, out_smem>>>(x, b_attn, sigma, out);
}